// round 3
// baseline (speedup 1.0000x reference)
#include <cuda_runtime.h>
#include <math.h>

// Problem constants (fixed by the reference)
#define HEAD_SIZE  128
#define HALF_ROT   64
#define NUM_TOKENS 8192
#define NUM_HEADS  32
#define NUM_KV     8
#define ROW        6144          // (32 + 2*8) * 128
#define V_OFF      5120          // (32+8)*128 ; V slice = 1024 floats = 256 float4
#define EPS        1e-6f

// inv_freq[d] = 10000^(-d/64), d = 0..63 — computed in double for correctly
// rounded fp32 values. c = ln(10000)/64 = 0.14391156831212787 (NOT 0.143841 —
// that wrong constant was Round 2's 0.70 rel_err).
__device__ float g_inv_freq[HALF_ROT];

__global__ void init_inv_freq_kernel() {
    int d = threadIdx.x;
    if (d < HALF_ROT) {
        const double c = 0.14391156831212787; // ln(10000)/64
        g_inv_freq[d] = (float)exp(-c * (double)d);
    }
}

__global__ __launch_bounds__(256, 8)
void rope_qknorm_kernel(const float* __restrict__ qkv,
                        const float* __restrict__ qw,
                        const float* __restrict__ kw,
                        const int*   __restrict__ pos,
                        float*       __restrict__ out)
{
    __shared__ float s_cos[HALF_ROT];
    __shared__ float s_sin[HALF_ROT];

    const int t    = blockIdx.x;
    const int tid  = threadIdx.x;
    const int lane = tid & 31;
    const int warp = tid >> 5;

    const float* row  = qkv + (size_t)t * ROW;
    float*       orow = out + (size_t)t * ROW;

    // --- cos/sin table for this token (threads 0..63) ---
    if (tid < HALF_ROT) {
        // fp32 multiply matches the reference's fp32 freqs rounding
        float ang = (float)pos[t] * g_inv_freq[tid];
        float s, c;
        sincosf(ang, &s, &c);
        s_cos[tid] = c;
        s_sin[tid] = s;
    }

    // --- V passthrough copy: exactly 1024 floats = 256 float4 ---
    {
        const float4* vin  = (const float4*)(row  + V_OFF);
        float4*       vout = (float4*)(orow + V_OFF);
        vout[tid] = vin[tid];
    }

    __syncthreads();

    // --- per-lane invariants (same for all heads in this block) ---
    const int dlo = 4 * (lane & 15);                 // rotary dim base 0..60
    const float4 cs = *(const float4*)(s_cos + dlo);
    const float4 sn = *(const float4*)(s_sin + dlo);
    const float  sgn = (lane < 16) ? -1.0f : 1.0f;   // x1*c - x2*s | x2*c + x1*s

    const float4 wq = ((const float4*)qw)[lane];
    const float4 wk = ((const float4*)kw)[lane];

    // --- 5 heads per warp: rmsnorm + neox rope, fully in registers ---
    #pragma unroll
    for (int i = 0; i < 5; i++) {
        const int h = warp * 5 + i;                  // 0..39
        const float4 x = ((const float4*)(row + h * HEAD_SIZE))[lane];

        float ss = x.x * x.x + x.y * x.y + x.z * x.z + x.w * x.w;
        #pragma unroll
        for (int o = 16; o; o >>= 1)
            ss += __shfl_xor_sync(0xffffffffu, ss, o);

        const float inv = rsqrtf(ss * (1.0f / 128.0f) + EPS);
        const float4 w  = (h < NUM_HEADS) ? wq : wk;

        float4 y;
        y.x = x.x * inv * w.x;
        y.y = x.y * inv * w.y;
        y.z = x.z * inv * w.z;
        y.w = x.w * inv * w.w;

        // partner half: dim i <-> i+64 lives exactly 16 lanes away
        float4 p;
        p.x = __shfl_xor_sync(0xffffffffu, y.x, 16);
        p.y = __shfl_xor_sync(0xffffffffu, y.y, 16);
        p.z = __shfl_xor_sync(0xffffffffu, y.z, 16);
        p.w = __shfl_xor_sync(0xffffffffu, y.w, 16);

        float4 r;
        r.x = fmaf(sgn * p.x, sn.x, y.x * cs.x);
        r.y = fmaf(sgn * p.y, sn.y, y.y * cs.y);
        r.z = fmaf(sgn * p.z, sn.z, y.z * cs.z);
        r.w = fmaf(sgn * p.w, sn.w, y.w * cs.w);

        ((float4*)(orow + h * HEAD_SIZE))[lane] = r;
    }
}

extern "C" void kernel_launch(void* const* d_in, const int* in_sizes, int n_in,
                              void* d_out, int out_size) {
    const float* qkv = (const float*)d_in[0];
    const float* qw  = (const float*)d_in[1];
    const float* kw  = (const float*)d_in[2];
    const int*   pos = (const int*)d_in[3];
    float* out = (float*)d_out;

    init_inv_freq_kernel<<<1, 64>>>();
    rope_qknorm_kernel<<<NUM_TOKENS, 256>>>(qkv, qw, kw, pos, out);
}

// round 4
// speedup vs baseline: 1.0118x; 1.0118x over previous
#include <cuda_runtime.h>
#include <math.h>

// Problem constants (fixed by the reference)
#define HEAD_SIZE  128
#define HALF_ROT   64
#define NUM_TOKENS 8192
#define NUM_HEADS  32
#define NUM_KV     8
#define ROW        6144          // (32 + 2*8) * 128
#define V_OFF      5120          // (32+8)*128 ; V slice = 1024 floats = 256 float4
#define EPS        1e-6f

__global__ __launch_bounds__(256, 4)
void rope_qknorm_kernel(const float* __restrict__ qkv,
                        const float* __restrict__ qw,
                        const float* __restrict__ kw,
                        const int*   __restrict__ pos,
                        float*       __restrict__ out)
{
    __shared__ float s_cos[HALF_ROT];
    __shared__ float s_sin[HALF_ROT];

    const int t    = blockIdx.x;
    const int tid  = threadIdx.x;
    const int lane = tid & 31;
    const int warp = tid >> 5;

    const float* row  = qkv + (size_t)t * ROW;
    float*       orow = out + (size_t)t * ROW;

    // Issue pos load ASAP (gates the sincos -> barrier chain)
    int p = 0;
    if (tid < HALF_ROT) p = pos[t];

    // --- V passthrough (independent; issue early, streaming) ---
    {
        const float4* vin  = (const float4*)(row  + V_OFF);
        float4*       vout = (float4*)(orow + V_OFF);
        float4 v = __ldcs(vin + tid);
        __stcs(vout + tid, v);
    }

    // --- Issue all 5 head loads BEFORE the barrier: 5-6 LDGs in flight/warp ---
    float4 y[5];
    #pragma unroll
    for (int i = 0; i < 5; i++) {
        const int h = warp * 5 + i;                  // 0..39
        y[i] = __ldcs((const float4*)(row + h * HEAD_SIZE) + lane);
    }

    const float4 wq = ((const float4*)qw)[lane];
    const float4 wk = ((const float4*)kw)[lane];

    // --- cos/sin table (threads 0..63); exp overlaps the in-flight LDGs ---
    // inv_freq[d] = 10000^(-d/64), double exp for correctly rounded fp32
    // (c = ln(10000)/64 = 0.14391156831212787)
    if (tid < HALF_ROT) {
        const double c = 0.14391156831212787;
        float invf = (float)exp(-c * (double)tid);
        float ang = (float)p * invf;   // fp32 product matches reference rounding
        float s, cc;
        sincosf(ang, &s, &cc);
        s_cos[tid] = cc;
        s_sin[tid] = s;
    }

    // --- rmsnorm each head in registers (pre-barrier, no cos/sin needed) ---
    #pragma unroll
    for (int i = 0; i < 5; i++) {
        const int h = warp * 5 + i;
        float ss = y[i].x * y[i].x + y[i].y * y[i].y
                 + y[i].z * y[i].z + y[i].w * y[i].w;
        #pragma unroll
        for (int o = 16; o; o >>= 1)
            ss += __shfl_xor_sync(0xffffffffu, ss, o);

        const float inv = rsqrtf(ss * (1.0f / 128.0f) + EPS);
        const float4 w  = (h < NUM_HEADS) ? wq : wk;
        y[i].x *= inv * w.x;
        y[i].y *= inv * w.y;
        y[i].z *= inv * w.z;
        y[i].w *= inv * w.w;
    }

    __syncthreads();

    // --- per-lane rope invariants ---
    const int dlo = 4 * (lane & 15);                 // rotary dim base 0..60
    const float4 cs = *(const float4*)(s_cos + dlo);
    const float4 sn = *(const float4*)(s_sin + dlo);
    const float  sgn = (lane < 16) ? -1.0f : 1.0f;   // x1*c - x2*s | x2*c + x1*s

    // --- rope + streaming store ---
    #pragma unroll
    for (int i = 0; i < 5; i++) {
        const int h = warp * 5 + i;

        // partner half: dim i <-> i+64 lives exactly 16 lanes away
        float4 pr;
        pr.x = __shfl_xor_sync(0xffffffffu, y[i].x, 16);
        pr.y = __shfl_xor_sync(0xffffffffu, y[i].y, 16);
        pr.z = __shfl_xor_sync(0xffffffffu, y[i].z, 16);
        pr.w = __shfl_xor_sync(0xffffffffu, y[i].w, 16);

        float4 r;
        r.x = fmaf(sgn * pr.x, sn.x, y[i].x * cs.x);
        r.y = fmaf(sgn * pr.y, sn.y, y[i].y * cs.y);
        r.z = fmaf(sgn * pr.z, sn.z, y[i].z * cs.z);
        r.w = fmaf(sgn * pr.w, sn.w, y[i].w * cs.w);

        __stcs((float4*)(orow + h * HEAD_SIZE) + lane, r);
    }
}

extern "C" void kernel_launch(void* const* d_in, const int* in_sizes, int n_in,
                              void* d_out, int out_size) {
    const float* qkv = (const float*)d_in[0];
    const float* qw  = (const float*)d_in[1];
    const float* kw  = (const float*)d_in[2];
    const int*   pos = (const int*)d_in[3];
    float* out = (float*)d_out;

    rope_qknorm_kernel<<<NUM_TOKENS, 256>>>(qkv, qw, kw, pos, out);
}